// round 14
// baseline (speedup 1.0000x reference)
#include <cuda_runtime.h>
#include <math.h>
#include <stdint.h>

// Problem constants
#define BSZ 64
#define SEQ 512
#define DIM 768
#define NSPANS 1280
#define LMAX 5
#define H 200
#define G4 800          // 4*H
#define NENT 16
#define MROWS (NSPANS*LMAX)   // 6400

// Scratch (device globals)
__device__ float d_xg    [2ll * MROWS * G4];
__device__ float d_h     [2ll * 2 * NSPANS * H];   // [parity][dir][n][hh]
__device__ float d_c     [2ll * NSPANS * H];
__device__ float d_sum   [2ll * NSPANS * H];
__device__ int   d_offset[NSPANS + 1];
__device__ int   d_rowmap[MROWS];

#define HBUF (2ll * NSPANS * H)

// ---------------------------------------------------------------------------
// tf32 / mma helpers
// ---------------------------------------------------------------------------
__device__ __forceinline__ uint32_t f2tf32(float f) {
    uint32_t r;
    asm("cvt.rna.tf32.f32 %0, %1;" : "=r"(r) : "f"(f));
    return r;
}

__device__ __forceinline__ void mma_tf32(float* c, const uint32_t* a, const uint32_t* b) {
    asm volatile(
        "mma.sync.aligned.m16n8k8.row.col.f32.tf32.tf32.f32 "
        "{%0,%1,%2,%3}, {%4,%5,%6,%7}, {%8,%9}, {%0,%1,%2,%3};"
        : "+f"(c[0]), "+f"(c[1]), "+f"(c[2]), "+f"(c[3])
        : "r"(a[0]), "r"(a[1]), "r"(a[2]), "r"(a[3]), "r"(b[0]), "r"(b[1]));
}

__device__ __forceinline__ float sigm(float x) { return 1.f / (1.f + expf(-x)); }

#define BK 32
#define PAD 4
#define LDSROW (BK + PAD)      // 36 (xg kernel)
#define BK2 64
#define LDSROW2 (BK2 + PAD)    // 68; 68 % 32 == 4 -> conflict-free frag LDS

// ---------------------------------------------------------------------------
// Compaction: offsets = exclusive-prefix(slen); rowmap[off+l] = (n<<3)|l
// ---------------------------------------------------------------------------
__global__ void compact_kernel(const int* __restrict__ slen)
{
    __shared__ int part[256];
    int tid = threadIdx.x;
    int base = tid * 5;
    int loc[5], s = 0;
#pragma unroll
    for (int i = 0; i < 5; i++) { loc[i] = s; s += slen[base + i]; }
    part[tid] = s;
    __syncthreads();
    for (int off = 1; off < 256; off <<= 1) {
        int v = (tid >= off) ? part[tid - off] : 0;
        __syncthreads();
        part[tid] += v;
        __syncthreads();
    }
    int pre = (tid == 0) ? 0 : part[tid - 1];
#pragma unroll
    for (int i = 0; i < 5; i++) {
        int n = base + i;
        int off = pre + loc[i];
        d_offset[n] = off;
        int ln = slen[n];
        for (int l = 0; l < ln; l++)
            d_rowmap[off + l] = (n << 3) | l;
    }
    if (tid == 255) d_offset[NSPANS] = part[255];
}

// ---------------------------------------------------------------------------
// xg GEMM, fused gather, compacted rows (R8 proven: BM=128, BN=64)
// ---------------------------------------------------------------------------
__global__ __launch_bounds__(256)
void gemm_xg_kernel(const float* __restrict__ hidden,
                    const int* __restrict__ tok,
                    const int* __restrict__ slen,
                    const int* __restrict__ sbatch,
                    const float* __restrict__ Wf, const float* __restrict__ bif,
                    const float* __restrict__ bhf,
                    const float* __restrict__ Wb, const float* __restrict__ bib,
                    const float* __restrict__ bhb)
{
    const int BM = 128, BN = 64, K = DIM, N = G4;
    int m0 = blockIdx.y * BM;
    int count = d_offset[NSPANS];
    if (m0 >= count) return;

    __shared__ uint32_t As[BM][LDSROW];
    __shared__ uint32_t Bs[BN][LDSROW];
    __shared__ const float* rowptr[BM];

    int dir = blockIdx.z;
    const float* W  = dir ? Wb : Wf;
    const float* c1 = dir ? bib : bif;
    const float* c2 = dir ? bhb : bhf;
    float* C        = d_xg + (size_t)dir * MROWS * G4;

    int tid  = threadIdx.x;
    int warp = tid >> 5, lane = tid & 31;
    int wm = warp & 3, wn = warp >> 2;
    int grp = lane >> 2, qid = lane & 3;
    int n0 = blockIdx.x * BN;

    if (tid < BM) {
        int r = m0 + tid;
        const float* p = nullptr;
        if (r < count) {
            int rm = d_rowmap[r];
            int n  = rm >> 3;
            int l  = rm & 7;
            int ln = slen[n];
            int sl = dir ? (ln - 1 - l) : l;
            int t  = tok[n * LMAX + sl];
            int b  = sbatch[n];
            p = hidden + ((size_t)b * SEQ + t) * DIM;
        }
        rowptr[tid] = p;
    }
    __syncthreads();

    float acc[2][4][4];
#pragma unroll
    for (int i = 0; i < 2; i++)
#pragma unroll
        for (int j = 0; j < 4; j++)
#pragma unroll
            for (int q = 0; q < 4; q++) acc[i][j][q] = 0.f;

    const int lrow = tid >> 3;
    const int lcol = (tid & 7) * 4;

    for (int kt = 0; kt < K; kt += BK) {
#pragma unroll
        for (int p = 0; p < BM / 32; p++) {
            int m = lrow + p * 32;
            const float* src = rowptr[m];
            float4 v = make_float4(0.f, 0.f, 0.f, 0.f);
            if (src)
                v = *(const float4*)(src + kt + lcol);
            uint4 t;
            t.x = f2tf32(v.x); t.y = f2tf32(v.y);
            t.z = f2tf32(v.z); t.w = f2tf32(v.w);
            *(uint4*)&As[m][lcol] = t;
        }
#pragma unroll
        for (int p = 0; p < BN / 32; p++) {
            int n = lrow + p * 32;
            float4 v = make_float4(0.f, 0.f, 0.f, 0.f);
            if (n0 + n < N)
                v = *(const float4*)(W + (size_t)(n0 + n) * DIM + kt + lcol);
            uint4 t;
            t.x = f2tf32(v.x); t.y = f2tf32(v.y);
            t.z = f2tf32(v.z); t.w = f2tf32(v.w);
            *(uint4*)&Bs[n][lcol] = t;
        }
        __syncthreads();

#pragma unroll
        for (int ks = 0; ks < BK / 8; ks++) {
            uint32_t af[2][4], bf[4][2];
#pragma unroll
            for (int i = 0; i < 2; i++) {
                int mr = wm * 32 + i * 16;
                af[i][0] = As[mr + grp    ][ks * 8 + qid    ];
                af[i][1] = As[mr + grp + 8][ks * 8 + qid    ];
                af[i][2] = As[mr + grp    ][ks * 8 + qid + 4];
                af[i][3] = As[mr + grp + 8][ks * 8 + qid + 4];
            }
#pragma unroll
            for (int j = 0; j < 4; j++) {
                int nr = wn * 32 + j * 8;
                bf[j][0] = Bs[nr + grp][ks * 8 + qid    ];
                bf[j][1] = Bs[nr + grp][ks * 8 + qid + 4];
            }
#pragma unroll
            for (int i = 0; i < 2; i++)
#pragma unroll
                for (int j = 0; j < 4; j++)
                    mma_tf32(acc[i][j], af[i], bf[j]);
        }
        __syncthreads();
    }

#pragma unroll
    for (int i = 0; i < 2; i++) {
#pragma unroll
        for (int j = 0; j < 4; j++) {
            int m = m0 + wm * 32 + i * 16 + grp;
            int n = n0 + wn * 32 + j * 8 + qid * 2;
            if (n < N) {
                float bb0 = c1[n] + c2[n];
                float bb1 = c1[n + 1] + c2[n + 1];
                C[(size_t)m * G4 + n]           = acc[i][j][0] + bb0;
                C[(size_t)m * G4 + n + 1]       = acc[i][j][1] + bb1;
                C[(size_t)(m + 8) * G4 + n]     = acc[i][j][2] + bb0;
                C[(size_t)(m + 8) * G4 + n + 1] = acc[i][j][3] + bb1;
            }
        }
    }
}

// ---------------------------------------------------------------------------
// Fused hh GEMM + cell, BK2=64 (4 serialized k-tiles instead of 7).
// BM=64 spans, BN=64 = 4 gates x 16 hh; 8 warps (2Mx4N), warp tile 32x16.
// Gs aliases tile smem after the mainloop. grid = (13, 20, 2)
// ---------------------------------------------------------------------------
__global__ __launch_bounds__(256)
void gemm_hh_cell_kernel(const float* __restrict__ Wf, const float* __restrict__ Wb,
                         const int* __restrict__ slen, int t)
{
    const int BM = 64, BN = 64, K = H;

    __shared__ uint32_t Tiles[(BM + BN) * LDSROW2];   // 34816 B; A then B
    float* Gs = (float*)Tiles;                        // alias after mainloop [BM][68]
    __shared__ int xrow[BM];
    __shared__ int lens[BM];

    uint32_t* As = Tiles;
    uint32_t* Bs = Tiles + BM * LDSROW2;

    int dir = blockIdx.z;
    const float* A     = d_h + ((t - 1) & 1) * HBUF + (size_t)dir * NSPANS * H;
    float*       h_out = d_h + (t & 1) * HBUF;
    const float* W  = dir ? Wb : Wf;
    const float* XG = d_xg + (size_t)dir * MROWS * G4;

    int tid  = threadIdx.x;
    int warp = tid >> 5, lane = tid & 31;
    int wm = warp & 1, wn = warp >> 1;
    int grp = lane >> 2, qid = lane & 3;
    int m0 = blockIdx.y * BM;
    int hh_base = blockIdx.x * 16;

    if (tid < BM) {
        int n  = m0 + tid;
        int ln = slen[n];
        lens[tid] = ln;
        int tt = t < ln ? t : (ln - 1);
        xrow[tid] = d_offset[n] + tt;
    }

    float acc[2][2][4];
#pragma unroll
    for (int i = 0; i < 2; i++)
#pragma unroll
        for (int j = 0; j < 2; j++)
#pragma unroll
            for (int q = 0; q < 4; q++) acc[i][j][q] = 0.f;

    // Tile loads: 64 rows x 64 cols, 16 float4-chunks/row, 16 rows per pass
    const int lrow = tid >> 4;          // 0..15
    const int lcol = (tid & 15) * 4;    // 0..60

    for (int kt = 0; kt < K; kt += BK2) {
        // A tile
#pragma unroll
        for (int p = 0; p < BM / 16; p++) {
            int m = lrow + p * 16;
            int k = kt + lcol;
            float4 v = make_float4(0.f, 0.f, 0.f, 0.f);
            if (k < K)
                v = *(const float4*)(A + (size_t)(m0 + m) * H + k);
            uint4 tt;
            tt.x = f2tf32(v.x); tt.y = f2tf32(v.y);
            tt.z = f2tf32(v.z); tt.w = f2tf32(v.w);
            *(uint4*)&As[m * LDSROW2 + lcol] = tt;
        }
        // B tile: row map n -> (n>>4)*H + hh_base + (n&15)
#pragma unroll
        for (int p = 0; p < BN / 16; p++) {
            int n = lrow + p * 16;
            int hhi = hh_base + (n & 15);
            int grow = (n >> 4) * H + hhi;
            int k = kt + lcol;
            float4 v = make_float4(0.f, 0.f, 0.f, 0.f);
            if (hhi < H && k < K)
                v = *(const float4*)(W + (size_t)grow * H + k);
            uint4 tt;
            tt.x = f2tf32(v.x); tt.y = f2tf32(v.y);
            tt.z = f2tf32(v.z); tt.w = f2tf32(v.w);
            *(uint4*)&Bs[n * LDSROW2 + lcol] = tt;
        }
        __syncthreads();

#pragma unroll
        for (int ks = 0; ks < BK2 / 8; ks++) {
            uint32_t af[2][4], bf[2][2];
#pragma unroll
            for (int i = 0; i < 2; i++) {
                int mr = wm * 32 + i * 16;
                af[i][0] = As[(mr + grp    ) * LDSROW2 + ks * 8 + qid    ];
                af[i][1] = As[(mr + grp + 8) * LDSROW2 + ks * 8 + qid    ];
                af[i][2] = As[(mr + grp    ) * LDSROW2 + ks * 8 + qid + 4];
                af[i][3] = As[(mr + grp + 8) * LDSROW2 + ks * 8 + qid + 4];
            }
#pragma unroll
            for (int j = 0; j < 2; j++) {
                int nr = wn * 16 + j * 8;
                bf[j][0] = Bs[(nr + grp) * LDSROW2 + ks * 8 + qid    ];
                bf[j][1] = Bs[(nr + grp) * LDSROW2 + ks * 8 + qid + 4];
            }
#pragma unroll
            for (int i = 0; i < 2; i++)
#pragma unroll
                for (int j = 0; j < 2; j++)
                    mma_tf32(acc[i][j], af[i], bf[j]);
        }
        __syncthreads();
    }

    // Stage gate tile into aliased Gs
#pragma unroll
    for (int i = 0; i < 2; i++) {
#pragma unroll
        for (int j = 0; j < 2; j++) {
            int m = wm * 32 + i * 16 + grp;
            int n = wn * 16 + j * 8 + qid * 2;
            Gs[m * 68 + n]           = acc[i][j][0];
            Gs[m * 68 + n + 1]       = acc[i][j][1];
            Gs[(m + 8) * 68 + n]     = acc[i][j][2];
            Gs[(m + 8) * 68 + n + 1] = acc[i][j][3];
        }
    }
    __syncthreads();

    // Cell phase: 64 spans x 16 hh, 4 items per thread
#pragma unroll
    for (int it = 0; it < 4; it++) {
        int id = tid + it * 256;
        int m  = id >> 4;
        int hl = id & 15;
        int hhi = hh_base + hl;
        if (hhi >= H) continue;

        size_t xb = (size_t)xrow[m] * G4 + hhi;
        float gi = Gs[m * 68 + hl     ] + XG[xb];
        float gf = Gs[m * 68 + 16 + hl] + XG[xb + H];
        float gg = Gs[m * 68 + 32 + hl] + XG[xb + 2 * H];
        float go = Gs[m * 68 + 48 + hl] + XG[xb + 3 * H];

        size_t sidx = (size_t)dir * NSPANS * H + (size_t)(m0 + m) * H + hhi;
        float cn = sigm(gf) * d_c[sidx] + sigm(gi) * tanhf(gg);
        float hn = sigm(go) * tanhf(cn);
        d_c[sidx]   = cn;
        h_out[sidx] = hn;
        if (t < lens[m]) d_sum[sidx] += hn;
    }
}

// ---------------------------------------------------------------------------
// t=0 cell: gates = xg[offset[n]] (h=0). Writes h parity 0, c, sum.
// ---------------------------------------------------------------------------
__global__ void lstm_cell0(const int* __restrict__ slen)
{
    int idx = blockIdx.x * blockDim.x + threadIdx.x;
    if (idx >= 2 * NSPANS * H) return;
    int hh  = idx % H;
    int n   = (idx / H) % NSPANS;
    int dir = idx / (H * NSPANS);

    int row = d_offset[n];
    const float* g = d_xg + (size_t)dir * MROWS * G4 + (size_t)row * G4;
    float gi = g[hh];
    float gg = g[2 * H + hh];
    float go = g[3 * H + hh];

    float cn = sigm(gi) * tanhf(gg);
    float hn = sigm(go) * tanhf(cn);
    d_c[idx] = cn;
    d_h[idx] = hn;                  // parity 0
    d_sum[idx] = hn;                // slen >= 1
}

// ---------------------------------------------------------------------------
// Logits with smem-staged E. 512 threads, 32 spans x 16 ents. grid = 40.
// ---------------------------------------------------------------------------
__global__ __launch_bounds__(512)
void logits_kernel(const float* __restrict__ E, float* __restrict__ out)
{
    __shared__ float Es[NENT * 2 * H];
    int tid = threadIdx.x;
    for (int i = tid; i < NENT * 2 * H; i += 512)
        Es[i] = E[i];
    __syncthreads();

    int s = tid >> 4;
    int e = tid & 15;
    int n = blockIdx.x * 32 + s;

    const float4* sf = (const float4*)(d_sum + (size_t)n * H);
    const float4* sb = (const float4*)(d_sum + (size_t)NSPANS * H + (size_t)n * H);
    const float4* er = (const float4*)(Es + e * 2 * H);

    float acc = 0.f;
#pragma unroll
    for (int j = 0; j < H / 4; j++) {
        float4 a = sf[j], b = er[j];
        acc += a.x * b.x + a.y * b.y + a.z * b.z + a.w * b.w;
    }
#pragma unroll
    for (int j = 0; j < H / 4; j++) {
        float4 a = sb[j], b = er[H / 4 + j];
        acc += a.x * b.x + a.y * b.y + a.z * b.z + a.w * b.w;
    }
    out[n * NENT + e] = acc;
}

// ---------------------------------------------------------------------------
// Launch
// ---------------------------------------------------------------------------
extern "C" void kernel_launch(void* const* d_in, const int* in_sizes, int n_in,
                              void* d_out, int out_size)
{
    const float* hidden = (const float*)d_in[0];
    const int*   tok    = (const int*)d_in[1];
    const int*   slen   = (const int*)d_in[2];
    const int*   sbatch = (const int*)d_in[3];
    const float* W_ih_f = (const float*)d_in[4];
    const float* W_hh_f = (const float*)d_in[5];
    const float* b_ih_f = (const float*)d_in[6];
    const float* b_hh_f = (const float*)d_in[7];
    const float* W_ih_b = (const float*)d_in[8];
    const float* W_hh_b = (const float*)d_in[9];
    const float* b_ih_b = (const float*)d_in[10];
    const float* b_hh_b = (const float*)d_in[11];
    const float* E      = (const float*)d_in[12];
    float* out          = (float*)d_out;

    // 0. Compaction
    compact_kernel<<<1, 256>>>(slen);

    // 1. xg GEMM, fused gather, compacted rows: grid 13 x 50 x 2 (self-trim)
    {
        dim3 grid((G4 + 63) / 64, MROWS / 128, 2);
        gemm_xg_kernel<<<grid, 256>>>(hidden, tok, slen, sbatch,
                                      W_ih_f, b_ih_f, b_hh_f,
                                      W_ih_b, b_ih_b, b_hh_b);
    }

    // 2. Recurrence
    {
        const int ct = 256;
        lstm_cell0<<<(2 * NSPANS * H + ct - 1) / ct, ct>>>(slen);
    }
    for (int t = 1; t < LMAX; t++) {
        dim3 grid((H + 15) / 16, NSPANS / 64, 2);   // 13 x 20 x 2
        gemm_hh_cell_kernel<<<grid, 256>>>(W_hh_f, W_hh_b, slen, t);
    }

    // 3. Logits
    logits_kernel<<<NSPANS / 32, 512>>>(E, out);
}